// round 3
// baseline (speedup 1.0000x reference)
#include <cuda_runtime.h>
#include <cuda_bf16.h>
#include <cstdint>

#define NU 200000
#define NI 100000
#define NE 1000000
#define HD 64
#define OD 32

// ---------------- device scratch (static globals: allocation-guard safe) ----------------
__device__ float g_hu[(size_t)NU * HD];   // pre-linear users / layer-2 output (overwrite)
__device__ float g_hi[(size_t)NI * HD];
__device__ float g_x1u[(size_t)NU * HD];
__device__ float g_x1i[(size_t)NI * HD];
__device__ float g_accu[(size_t)NU * HD];
__device__ float g_acci[(size_t)NI * HD];
__device__ float g_idegu[NU];             // deg, then 1/max(deg,1)
__device__ float g_idegi[NI];

// ---------------- utility kernels ----------------
__global__ void zero_kernel(float* __restrict__ p, size_t n4) {
    size_t i = (size_t)blockIdx.x * blockDim.x + threadIdx.x;
    if (i < n4) ((float4*)p)[i] = make_float4(0.f, 0.f, 0.f, 0.f);
}

__global__ void count_kernel(const int* __restrict__ ei, int nedges, float* __restrict__ deg) {
    int e = blockIdx.x * blockDim.x + threadIdx.x;
    if (e < nedges) atomicAdd(&deg[ei[nedges + e]], 1.0f);
}

__global__ void invert_kernel(float* __restrict__ p, int n) {
    int i = blockIdx.x * blockDim.x + threadIdx.x;
    if (i < n) p[i] = 1.0f / fmaxf(p[i], 1.0f);
}

// ---------------- scatter: acc[dst] += feat[src] (vector RED, 16 threads/edge) ----------------
__global__ void scatter_kernel(const float* __restrict__ feat, const int* __restrict__ ei,
                               int nedges, float* __restrict__ acc) {
    long long idx = (long long)blockIdx.x * blockDim.x + threadIdx.x;
    if (idx >= (long long)nedges * 16) return;
    int e = (int)(idx >> 4);
    int q = (int)(idx & 15);
    int s = __ldg(ei + e);
    int d = __ldg(ei + nedges + e);
    float4 v = __ldg((const float4*)(feat + (size_t)s * HD) + q);
    float* dptr = acc + (size_t)d * HD + (size_t)q * 4;
    asm volatile("red.global.add.v4.f32 [%0], {%1,%2,%3,%4};"
                 :: "l"(dptr), "f"(v.x), "f"(v.y), "f"(v.z), "f"(v.w) : "memory");
}

// ---------------- dense linear: out[n,COLS] = x[n,64] @ W[COLS,64]^T + b ----------------
template <int COLS>
__global__ void __launch_bounds__(256) linear_kernel(
    const float* __restrict__ x, const float* __restrict__ W,
    const float* __restrict__ bias, float* __restrict__ out, int n)
{
    constexpr int WS = COLS + 4;            // padded stride
    __shared__ float sW[64 * WS];           // <= 64*68*4 = 17408 B
    __shared__ float sX[64 * 68];           // 17408 B
    int tid = threadIdx.x;

    for (int i = tid; i < COLS * 64; i += 256) {
        int c = i >> 6, k = i & 63;         // W row-major [COLS][64], coalesced read
        sW[k * WS + c] = W[i];
    }
    int row0 = blockIdx.x * 64;
    for (int i = tid; i < 64 * 16; i += 256) {
        int r = i >> 4, q = i & 15;
        int row = row0 + r;
        float4 v = make_float4(0.f, 0.f, 0.f, 0.f);
        if (row < n) v = __ldg((const float4*)(x + (size_t)row * 64) + q);
        *(float4*)&sX[r * 68 + q * 4] = v;
    }
    __syncthreads();

    constexpr int CPT = COLS / 4;           // 16 (H) or 8 (OUT)
    int r = tid >> 2, sub = tid & 3;
    int c0 = sub * CPT;
    float o[CPT];
    #pragma unroll
    for (int i = 0; i < CPT; i++) o[i] = __ldg(bias + c0 + i);

    #pragma unroll 4
    for (int k = 0; k < 64; k++) {
        float xv = sX[r * 68 + k];
        #pragma unroll
        for (int i = 0; i < CPT / 4; i++) {
            float4 w = *(const float4*)&sW[k * WS + c0 + 4 * i];
            o[4 * i + 0] += xv * w.x;
            o[4 * i + 1] += xv * w.y;
            o[4 * i + 2] += xv * w.z;
            o[4 * i + 3] += xv * w.w;
        }
    }
    int row = row0 + r;
    if (row < n) {
        #pragma unroll
        for (int i = 0; i < CPT / 4; i++) {
            float4 v = make_float4(o[4 * i], o[4 * i + 1], o[4 * i + 2], o[4 * i + 3]);
            ((float4*)(out + (size_t)row * COLS + c0))[i] = v;
        }
    }
}

// ---- fused conv combine: out = relu( (acc*ideg) @ Wrel^T + b + h @ Wroot^T + h ) ----
// 32 KB static shared (weights only). Activations live in registers; the 4-thread
// row group exchanges them with width-4 shuffles. FMA-pipe bound (~2048 FFMA vs
// 128 SHFL per warp loop), so no smem-capacity opt-in needed.
__global__ void __launch_bounds__(256) combine_kernel(
    const float* __restrict__ acc, const float* __restrict__ ideg,
    const float* __restrict__ h,
    const float* __restrict__ Wrel, const float* __restrict__ brel,
    const float* __restrict__ Wroot,
    float* __restrict__ out, int n)
{
    __shared__ float sWrel[64 * 64];        // 16384 B, k-uniform reads -> broadcast, no conflicts
    __shared__ float sWroot[64 * 64];       // 16384 B
    int tid = threadIdx.x;

    for (int i = tid; i < 4096; i += 256) {
        int c = i >> 6, k = i & 63;         // W row-major [64][64]
        sWrel[k * 64 + c]  = Wrel[i];
        sWroot[k * 64 + c] = Wroot[i];
    }
    __syncthreads();

    int r = tid >> 2, sub = tid & 3;
    int row = blockIdx.x * 64 + r;
    bool valid = row < n;
    int rr = valid ? row : 0;               // clamp; invalid results discarded

    float id = __ldg(ideg + rr);
    const float4* ap = (const float4*)(acc + (size_t)rr * 64) + sub * 4;
    const float4* hp = (const float4*)(h   + (size_t)rr * 64) + sub * 4;
    float m[16], hh[16];
    #pragma unroll
    for (int i = 0; i < 4; i++) {
        float4 a  = __ldg(ap + i);
        float4 hv = __ldg(hp + i);
        m[4 * i + 0] = a.x * id;  m[4 * i + 1] = a.y * id;
        m[4 * i + 2] = a.z * id;  m[4 * i + 3] = a.w * id;
        hh[4 * i + 0] = hv.x;  hh[4 * i + 1] = hv.y;
        hh[4 * i + 2] = hv.z;  hh[4 * i + 3] = hv.w;
    }

    int c0 = sub * 16;
    float o[16];
    #pragma unroll
    for (int i = 0; i < 16; i++) o[i] = __ldg(brel + c0 + i);

    #pragma unroll
    for (int k = 0; k < 64; k++) {
        float mv = __shfl_sync(0xffffffffu, m[k & 15],  k >> 4, 4);
        float hv = __shfl_sync(0xffffffffu, hh[k & 15], k >> 4, 4);
        #pragma unroll
        for (int i = 0; i < 4; i++) {
            float4 wr = *(const float4*)&sWrel[k * 64 + c0 + 4 * i];
            float4 wo = *(const float4*)&sWroot[k * 64 + c0 + 4 * i];
            o[4 * i + 0] += mv * wr.x + hv * wo.x;
            o[4 * i + 1] += mv * wr.y + hv * wo.y;
            o[4 * i + 2] += mv * wr.z + hv * wo.z;
            o[4 * i + 3] += mv * wr.w + hv * wo.w;
        }
    }

    if (valid) {
        // hh holds exactly this thread's output quarter (c0 = sub*16): skip connection
        #pragma unroll
        for (int i = 0; i < 4; i++) {
            float4 v;
            v.x = fmaxf(o[4 * i + 0] + hh[4 * i + 0], 0.f);
            v.y = fmaxf(o[4 * i + 1] + hh[4 * i + 1], 0.f);
            v.z = fmaxf(o[4 * i + 2] + hh[4 * i + 2], 0.f);
            v.w = fmaxf(o[4 * i + 3] + hh[4 * i + 3], 0.f);
            ((float4*)(out + (size_t)row * 64 + c0))[i] = v;
        }
    }
}

// ---------------- host ----------------
extern "C" void kernel_launch(void* const* d_in, const int* in_sizes, int n_in,
                              void* d_out, int out_size)
{
    const float* x_user = (const float*)d_in[0];
    const float* x_item = (const float*)d_in[1];
    const int*   ei_u2i = (const int*)d_in[2];
    const int*   ei_i2u = (const int*)d_in[3];
    const float* pre_w_u = (const float*)d_in[4];
    const float* pre_b_u = (const float*)d_in[5];
    const float* pre_w_i = (const float*)d_in[6];
    const float* pre_b_i = (const float*)d_in[7];
    const float* c1u2i_wrel  = (const float*)d_in[8];
    const float* c1u2i_brel  = (const float*)d_in[9];
    const float* c1u2i_wroot = (const float*)d_in[10];
    const float* c1i2u_wrel  = (const float*)d_in[11];
    const float* c1i2u_brel  = (const float*)d_in[12];
    const float* c1i2u_wroot = (const float*)d_in[13];
    const float* c2u2i_wrel  = (const float*)d_in[14];
    const float* c2u2i_brel  = (const float*)d_in[15];
    const float* c2u2i_wroot = (const float*)d_in[16];
    const float* c2i2u_wrel  = (const float*)d_in[17];
    const float* c2i2u_brel  = (const float*)d_in[18];
    const float* c2i2u_wroot = (const float*)d_in[19];
    const float* post_w_u = (const float*)d_in[20];
    const float* post_b_u = (const float*)d_in[21];
    const float* post_w_i = (const float*)d_in[22];
    const float* post_b_i = (const float*)d_in[23];
    float* out_u = (float*)d_out;
    float* out_i = out_u + (size_t)NU * OD;

    float *hu, *hi, *x1u, *x1i, *au, *ai, *idu, *idi;
    cudaGetSymbolAddress((void**)&hu,  g_hu);
    cudaGetSymbolAddress((void**)&hi,  g_hi);
    cudaGetSymbolAddress((void**)&x1u, g_x1u);
    cudaGetSymbolAddress((void**)&x1i, g_x1i);
    cudaGetSymbolAddress((void**)&au,  g_accu);
    cudaGetSymbolAddress((void**)&ai,  g_acci);
    cudaGetSymbolAddress((void**)&idu, g_idegu);
    cudaGetSymbolAddress((void**)&idi, g_idegi);

    const int ZB = 256;
    const int NUB = (NU + 63) / 64;      // 3125
    const int NIB = (NI + 63) / 64;      // 1563
    const int EB  = (NE + 255) / 256;
    const long long sthreads = (long long)NE * 16;
    const int SB = (int)((sthreads + 255) / 256);

    // degrees (shared by both layers)
    zero_kernel<<<(NU / 4 + ZB - 1) / ZB, ZB>>>(idu, NU / 4);
    zero_kernel<<<(NI / 4 + ZB - 1) / ZB, ZB>>>(idi, NI / 4);
    count_kernel<<<EB, 256>>>(ei_u2i, NE, idi);
    count_kernel<<<EB, 256>>>(ei_i2u, NE, idu);
    invert_kernel<<<(NU + 255) / 256, 256>>>(idu, NU);
    invert_kernel<<<(NI + 255) / 256, 256>>>(idi, NI);

    // preprocess linears
    linear_kernel<64><<<NUB, 256>>>(x_user, pre_w_u, pre_b_u, hu, NU);
    linear_kernel<64><<<NIB, 256>>>(x_item, pre_w_i, pre_b_i, hi, NI);

    // layer 1 scatter
    zero_kernel<<<((size_t)NU * 16 + ZB - 1) / ZB, ZB>>>(au, (size_t)NU * 16);
    zero_kernel<<<((size_t)NI * 16 + ZB - 1) / ZB, ZB>>>(ai, (size_t)NI * 16);
    scatter_kernel<<<SB, 256>>>(hu, ei_u2i, NE, ai);
    scatter_kernel<<<SB, 256>>>(hi, ei_i2u, NE, au);

    // layer 1 combine
    combine_kernel<<<NIB, 256>>>(ai, idi, hi, c1u2i_wrel, c1u2i_brel, c1u2i_wroot, x1i, NI);
    combine_kernel<<<NUB, 256>>>(au, idu, hu, c1i2u_wrel, c1i2u_brel, c1i2u_wroot, x1u, NU);

    // layer 2 scatter
    zero_kernel<<<((size_t)NU * 16 + ZB - 1) / ZB, ZB>>>(au, (size_t)NU * 16);
    zero_kernel<<<((size_t)NI * 16 + ZB - 1) / ZB, ZB>>>(ai, (size_t)NI * 16);
    scatter_kernel<<<SB, 256>>>(x1u, ei_u2i, NE, ai);
    scatter_kernel<<<SB, 256>>>(x1i, ei_i2u, NE, au);

    // layer 2 combine (outputs overwrite the pre-linear buffers)
    combine_kernel<<<NIB, 256>>>(ai, idi, x1i, c2u2i_wrel, c2u2i_brel, c2u2i_wroot, hi, NI);
    combine_kernel<<<NUB, 256>>>(au, idu, x1u, c2i2u_wrel, c2i2u_brel, c2i2u_wroot, hu, NU);

    // postprocess linears -> output (out_u then out_i)
    linear_kernel<32><<<NUB, 256>>>(hu, post_w_u, post_b_u, out_u, NU);
    linear_kernel<32><<<NIB, 256>>>(hi, post_w_i, post_b_i, out_i, NI);
}

// round 4
// speedup vs baseline: 1.0675x; 1.0675x over previous
#include <cuda_runtime.h>
#include <cuda_bf16.h>
#include <cstdint>

#define NU 200000
#define NI 100000
#define NE 1000000
#define HD 64
#define OD 32
#define CHUNK 1024   // elements per scan block (256 threads * 4)

// ---------------- device scratch (static globals: allocation-guard safe) ----------------
__device__ float g_hu[(size_t)NU * HD];   // pre-linear users / layer-2 output (overwrite)
__device__ float g_hi[(size_t)NI * HD];
__device__ float g_x1u[(size_t)NU * HD];
__device__ float g_x1i[(size_t)NI * HD];
__device__ int   g_csr_u2i[NE];           // src ids grouped by item dst
__device__ int   g_csr_i2u[NE];           // src ids grouped by user dst
__device__ int   g_rsu[NU + 1];           // row_start users
__device__ int   g_rsi[NI + 1];           // row_start items
__device__ int   g_curu[NU];              // deg, then fill cursor
__device__ int   g_curi[NI];
__device__ int   g_part[256];             // scan partials (reused sequentially)

// ---------------- CSR build kernels ----------------
__global__ void zero_int_kernel(int* __restrict__ p, int n) {
    int i = blockIdx.x * blockDim.x + threadIdx.x;
    if (i < n) p[i] = 0;
}

__global__ void hist_kernel(const int* __restrict__ ei, int nedges, int* __restrict__ deg) {
    int e = blockIdx.x * blockDim.x + threadIdx.x;
    if (e < nedges) atomicAdd(&deg[ei[nedges + e]], 1);
}

// per-chunk sums: part[b] = sum of deg[b*CHUNK .. b*CHUNK+CHUNK)
__global__ void chunk_sum_kernel(const int* __restrict__ deg, int n, int* __restrict__ part) {
    __shared__ int sc[256];
    int b = blockIdx.x, tid = threadIdx.x;
    int base = b * CHUNK + tid * 4;
    int s = 0;
    #pragma unroll
    for (int j = 0; j < 4; j++) { int idx = base + j; if (idx < n) s += deg[idx]; }
    sc[tid] = s; __syncthreads();
    for (int d = 128; d; d >>= 1) { if (tid < d) sc[tid] += sc[tid + d]; __syncthreads(); }
    if (tid == 0) part[b] = sc[0];
}

// exclusive scan of part[0..nblk) in place (single block, nblk <= 256)
__global__ void scan_part_kernel(int* __restrict__ part, int nblk) {
    __shared__ int sc[256];
    int tid = threadIdx.x;
    int v = (tid < nblk) ? part[tid] : 0;
    sc[tid] = v; __syncthreads();
    for (int d = 1; d < 256; d <<= 1) {
        int t = (tid >= d) ? sc[tid - d] : 0;
        __syncthreads();
        sc[tid] += t;
        __syncthreads();
    }
    if (tid < nblk) part[tid] = sc[tid] - v;   // exclusive
}

// write exclusive scan: rs[i] = part[b] + excl_within_chunk; also cur[i] = rs[i]
__global__ void scan_write_kernel(const int* __restrict__ deg, int n,
                                  const int* __restrict__ part,
                                  int* __restrict__ rs, int* __restrict__ cur,
                                  int total) {
    __shared__ int sc[256];
    int b = blockIdx.x, tid = threadIdx.x;
    int base = b * CHUNK + tid * 4;
    int v[4]; int s = 0;
    #pragma unroll
    for (int j = 0; j < 4; j++) { int idx = base + j; v[j] = (idx < n) ? deg[idx] : 0; s += v[j]; }
    sc[tid] = s; __syncthreads();
    for (int d = 1; d < 256; d <<= 1) {
        int t = (tid >= d) ? sc[tid - d] : 0;
        __syncthreads();
        sc[tid] += t;
        __syncthreads();
    }
    int off = part[b] + (sc[tid] - s);
    #pragma unroll
    for (int j = 0; j < 4; j++) {
        int idx = base + j;
        if (idx < n) { rs[idx] = off; cur[idx] = off; }
        off += v[j];
    }
    if (b == 0 && tid == 0) rs[n] = total;
}

__global__ void fill_kernel(const int* __restrict__ ei, int nedges,
                            int* __restrict__ cur, int* __restrict__ csr) {
    int e = blockIdx.x * blockDim.x + threadIdx.x;
    if (e < nedges) {
        int src = ei[e];
        int dst = ei[nedges + e];
        int pos = atomicAdd(&cur[dst], 1);
        csr[pos] = src;
    }
}

// ---------------- dense linear: out[n,COLS] = x[n,64] @ W[COLS,64]^T + b ----------------
template <int COLS>
__global__ void __launch_bounds__(256) linear_kernel(
    const float* __restrict__ x, const float* __restrict__ W,
    const float* __restrict__ bias, float* __restrict__ out, int n)
{
    constexpr int WS = COLS + 4;
    __shared__ float sW[64 * WS];
    __shared__ float sX[64 * 68];
    int tid = threadIdx.x;

    for (int i = tid; i < COLS * 64; i += 256) {
        int c = i >> 6, k = i & 63;         // W row-major [COLS][64]
        sW[k * WS + c] = W[i];
    }
    int row0 = blockIdx.x * 64;
    for (int i = tid; i < 64 * 16; i += 256) {
        int r = i >> 4, q = i & 15;
        int row = row0 + r;
        float4 v = make_float4(0.f, 0.f, 0.f, 0.f);
        if (row < n) v = __ldg((const float4*)(x + (size_t)row * 64) + q);
        *(float4*)&sX[r * 68 + q * 4] = v;
    }
    __syncthreads();

    constexpr int CPT = COLS / 4;
    int r = tid >> 2, sub = tid & 3;
    int c0 = sub * CPT;
    float o[CPT];
    #pragma unroll
    for (int i = 0; i < CPT; i++) o[i] = __ldg(bias + c0 + i);

    #pragma unroll 4
    for (int k = 0; k < 64; k++) {
        float xv = sX[r * 68 + k];
        #pragma unroll
        for (int i = 0; i < CPT / 4; i++) {
            float4 w = *(const float4*)&sW[k * WS + c0 + 4 * i];
            o[4 * i + 0] += xv * w.x;
            o[4 * i + 1] += xv * w.y;
            o[4 * i + 2] += xv * w.z;
            o[4 * i + 3] += xv * w.w;
        }
    }
    int row = row0 + r;
    if (row < n) {
        #pragma unroll
        for (int i = 0; i < CPT / 4; i++) {
            float4 v = make_float4(o[4 * i], o[4 * i + 1], o[4 * i + 2], o[4 * i + 3]);
            ((float4*)(out + (size_t)row * COLS + c0))[i] = v;
        }
    }
}

// ---- fused CSR conv: out = relu( mean_{s in N(row)}(feat[s]) @ Wrel^T + b
//                                  + h[row] @ Wroot^T + h[row] ) ----
// 4 threads per dst row: CSR gather+accumulate in registers (no atomics, no acc
// buffers), then shuffle-broadcast dual 64x64 matvec against 32 KB smem weights.
__global__ void __launch_bounds__(256) combine_csr_kernel(
    const float* __restrict__ feat, const float* __restrict__ h,
    const int* __restrict__ rs, const int* __restrict__ csr,
    const float* __restrict__ Wrel, const float* __restrict__ brel,
    const float* __restrict__ Wroot,
    float* __restrict__ out, int n)
{
    __shared__ float sWrel[64 * 64];
    __shared__ float sWroot[64 * 64];
    int tid = threadIdx.x;

    for (int i = tid; i < 4096; i += 256) {
        int c = i >> 6, k = i & 63;
        sWrel[k * 64 + c]  = Wrel[i];
        sWroot[k * 64 + c] = Wroot[i];
    }
    __syncthreads();

    int r = tid >> 2, sub = tid & 3;
    int row = blockIdx.x * 64 + r;
    bool valid = row < n;
    int rr = valid ? row : 0;

    int e0 = __ldg(rs + rr), e1 = __ldg(rs + rr + 1);
    float m[16];
    #pragma unroll
    for (int i = 0; i < 16; i++) m[i] = 0.f;

    for (int e = e0; e < e1; e++) {
        int s = __ldg(csr + e);
        const float4* sp = (const float4*)(feat + (size_t)s * 64) + sub * 4;
        #pragma unroll
        for (int i = 0; i < 4; i++) {
            float4 v = __ldg(sp + i);
            m[4 * i + 0] += v.x;  m[4 * i + 1] += v.y;
            m[4 * i + 2] += v.z;  m[4 * i + 3] += v.w;
        }
    }
    float id = 1.f / fmaxf((float)(e1 - e0), 1.f);
    #pragma unroll
    for (int i = 0; i < 16; i++) m[i] *= id;

    float hh[16];
    const float4* hp = (const float4*)(h + (size_t)rr * 64) + sub * 4;
    #pragma unroll
    for (int i = 0; i < 4; i++) {
        float4 v = __ldg(hp + i);
        hh[4 * i + 0] = v.x;  hh[4 * i + 1] = v.y;
        hh[4 * i + 2] = v.z;  hh[4 * i + 3] = v.w;
    }

    int c0 = sub * 16;
    float o[16];
    #pragma unroll
    for (int i = 0; i < 16; i++) o[i] = __ldg(brel + c0 + i);

    #pragma unroll
    for (int k = 0; k < 64; k++) {
        float mv = __shfl_sync(0xffffffffu, m[k & 15],  k >> 4, 4);
        float hv = __shfl_sync(0xffffffffu, hh[k & 15], k >> 4, 4);
        #pragma unroll
        for (int i = 0; i < 4; i++) {
            float4 wr = *(const float4*)&sWrel[k * 64 + c0 + 4 * i];
            float4 wo = *(const float4*)&sWroot[k * 64 + c0 + 4 * i];
            o[4 * i + 0] += mv * wr.x + hv * wo.x;
            o[4 * i + 1] += mv * wr.y + hv * wo.y;
            o[4 * i + 2] += mv * wr.z + hv * wo.z;
            o[4 * i + 3] += mv * wr.w + hv * wo.w;
        }
    }

    if (valid) {
        #pragma unroll
        for (int i = 0; i < 4; i++) {
            float4 v;
            v.x = fmaxf(o[4 * i + 0] + hh[4 * i + 0], 0.f);
            v.y = fmaxf(o[4 * i + 1] + hh[4 * i + 1], 0.f);
            v.z = fmaxf(o[4 * i + 2] + hh[4 * i + 2], 0.f);
            v.w = fmaxf(o[4 * i + 3] + hh[4 * i + 3], 0.f);
            ((float4*)(out + (size_t)row * 64 + c0))[i] = v;
        }
    }
}

// ---------------- host ----------------
extern "C" void kernel_launch(void* const* d_in, const int* in_sizes, int n_in,
                              void* d_out, int out_size)
{
    const float* x_user = (const float*)d_in[0];
    const float* x_item = (const float*)d_in[1];
    const int*   ei_u2i = (const int*)d_in[2];
    const int*   ei_i2u = (const int*)d_in[3];
    const float* pre_w_u = (const float*)d_in[4];
    const float* pre_b_u = (const float*)d_in[5];
    const float* pre_w_i = (const float*)d_in[6];
    const float* pre_b_i = (const float*)d_in[7];
    const float* c1u2i_wrel  = (const float*)d_in[8];
    const float* c1u2i_brel  = (const float*)d_in[9];
    const float* c1u2i_wroot = (const float*)d_in[10];
    const float* c1i2u_wrel  = (const float*)d_in[11];
    const float* c1i2u_brel  = (const float*)d_in[12];
    const float* c1i2u_wroot = (const float*)d_in[13];
    const float* c2u2i_wrel  = (const float*)d_in[14];
    const float* c2u2i_brel  = (const float*)d_in[15];
    const float* c2u2i_wroot = (const float*)d_in[16];
    const float* c2i2u_wrel  = (const float*)d_in[17];
    const float* c2i2u_brel  = (const float*)d_in[18];
    const float* c2i2u_wroot = (const float*)d_in[19];
    const float* post_w_u = (const float*)d_in[20];
    const float* post_b_u = (const float*)d_in[21];
    const float* post_w_i = (const float*)d_in[22];
    const float* post_b_i = (const float*)d_in[23];
    float* out_u = (float*)d_out;
    float* out_i = out_u + (size_t)NU * OD;

    float *hu, *hi, *x1u, *x1i;
    int *csr_u2i, *csr_i2u, *rsu, *rsi, *curu, *curi, *part;
    cudaGetSymbolAddress((void**)&hu,  g_hu);
    cudaGetSymbolAddress((void**)&hi,  g_hi);
    cudaGetSymbolAddress((void**)&x1u, g_x1u);
    cudaGetSymbolAddress((void**)&x1i, g_x1i);
    cudaGetSymbolAddress((void**)&csr_u2i, g_csr_u2i);
    cudaGetSymbolAddress((void**)&csr_i2u, g_csr_i2u);
    cudaGetSymbolAddress((void**)&rsu,  g_rsu);
    cudaGetSymbolAddress((void**)&rsi,  g_rsi);
    cudaGetSymbolAddress((void**)&curu, g_curu);
    cudaGetSymbolAddress((void**)&curi, g_curi);
    cudaGetSymbolAddress((void**)&part, g_part);

    const int NUB = (NU + 63) / 64;
    const int NIB = (NI + 63) / 64;
    const int EB  = (NE + 255) / 256;
    const int NBLKU = (NU + CHUNK - 1) / CHUNK;   // 196
    const int NBLKI = (NI + CHUNK - 1) / CHUNK;   // 98

    // ---- CSR build: u2i (dst = items) ----
    zero_int_kernel<<<(NI + 255) / 256, 256>>>(curi, NI);
    hist_kernel<<<EB, 256>>>(ei_u2i, NE, curi);
    chunk_sum_kernel<<<NBLKI, 256>>>(curi, NI, part);
    scan_part_kernel<<<1, 256>>>(part, NBLKI);
    scan_write_kernel<<<NBLKI, 256>>>(curi, NI, part, rsi, curi, NE);
    fill_kernel<<<EB, 256>>>(ei_u2i, NE, curi, csr_u2i);

    // ---- CSR build: i2u (dst = users) ----
    zero_int_kernel<<<(NU + 255) / 256, 256>>>(curu, NU);
    hist_kernel<<<EB, 256>>>(ei_i2u, NE, curu);
    chunk_sum_kernel<<<NBLKU, 256>>>(curu, NU, part);
    scan_part_kernel<<<1, 256>>>(part, NBLKU);
    scan_write_kernel<<<NBLKU, 256>>>(curu, NU, part, rsu, curu, NE);
    fill_kernel<<<EB, 256>>>(ei_i2u, NE, curu, csr_i2u);

    // ---- preprocess linears ----
    linear_kernel<64><<<NUB, 256>>>(x_user, pre_w_u, pre_b_u, hu, NU);
    linear_kernel<64><<<NIB, 256>>>(x_item, pre_w_i, pre_b_i, hi, NI);

    // ---- layer 1 (fused gather+mean+dense+relu) ----
    combine_csr_kernel<<<NIB, 256>>>(hu, hi, rsi, csr_u2i,
                                     c1u2i_wrel, c1u2i_brel, c1u2i_wroot, x1i, NI);
    combine_csr_kernel<<<NUB, 256>>>(hi, hu, rsu, csr_i2u,
                                     c1i2u_wrel, c1i2u_brel, c1i2u_wroot, x1u, NU);

    // ---- layer 2 (outputs overwrite the pre-linear buffers) ----
    combine_csr_kernel<<<NIB, 256>>>(x1u, x1i, rsi, csr_u2i,
                                     c2u2i_wrel, c2u2i_brel, c2u2i_wroot, hi, NI);
    combine_csr_kernel<<<NUB, 256>>>(x1i, x1u, rsu, csr_i2u,
                                     c2i2u_wrel, c2i2u_brel, c2i2u_wroot, hu, NU);

    // ---- postprocess linears -> output ----
    linear_kernel<32><<<NUB, 256>>>(hu, post_w_u, post_b_u, out_u, NU);
    linear_kernel<32><<<NIB, 256>>>(hi, post_w_i, post_b_i, out_i, NI);
}